// round 2
// baseline (speedup 1.0000x reference)
#include <cuda_runtime.h>
#include <math.h>

#define N_ROWS 4096
#define D_IN   2048
#define D_HID  8192
#define D_OUT  2048
#define RANK   8

// ---------------------------------------------------------------------------
// Scratch (static device globals: no allocation in kernel_launch)
// ---------------------------------------------------------------------------
__device__ float g_u  [RANK * D_IN];                    // orthonormal Householder vectors
__device__ float g_xq [(size_t)N_ROWS * D_IN];          // x @ Q        (33.5 MB)
__device__ float g_h  [(size_t)N_ROWS * D_HID];         // gelu(xq@Wr)  (134 MB)

// ---------------------------------------------------------------------------
// Block reduction (256 threads)
// ---------------------------------------------------------------------------
__device__ __forceinline__ float blockReduceSum256(float v, float* sred) {
    #pragma unroll
    for (int o = 16; o > 0; o >>= 1) v += __shfl_down_sync(0xffffffffu, v, o);
    const int lane = threadIdx.x & 31;
    const int warp = threadIdx.x >> 5;
    if (lane == 0) sred[warp] = v;
    __syncthreads();
    if (threadIdx.x == 0) {
        float r = sred[0];
        #pragma unroll
        for (int i = 1; i < 8; i++) r += sred[i];
        sred[0] = r;
    }
    __syncthreads();
    float r = sred[0];
    __syncthreads();
    return r;
}

// ---------------------------------------------------------------------------
// 1) Modified Gram-Schmidt on hra_u [D_IN x RANK] (column i at stride RANK)
//    Single block, 256 threads. Matches reference: sequential projections,
//    normalize by 1/(||u|| + 1e-6).
// ---------------------------------------------------------------------------
__global__ void gs_kernel(const float* __restrict__ hra_u, float* __restrict__ u_out) {
    __shared__ float cur[D_IN];
    __shared__ float sred[8];
    const int tid = threadIdx.x;

    for (int i = 0; i < RANK; i++) {
        for (int d = tid; d < D_IN; d += 256) cur[d] = hra_u[(size_t)d * RANK + i];
        __syncthreads();

        for (int j = 0; j < i; j++) {
            const float* uj = u_out + (size_t)j * D_IN;
            float local = 0.f;
            for (int d = tid; d < D_IN; d += 256) local += uj[d] * cur[d];
            float dot = blockReduceSum256(local, sred);   // includes barrier after reads
            for (int d = tid; d < D_IN; d += 256) cur[d] -= dot * uj[d];
            __syncthreads();
        }

        float local = 0.f;
        for (int d = tid; d < D_IN; d += 256) local += cur[d] * cur[d];
        float nrm2 = blockReduceSum256(local, sred);
        float inv = 1.0f / (sqrtf(nrm2) + 1e-6f);
        for (int d = tid; d < D_IN; d += 256) u_out[(size_t)i * D_IN + d] = cur[d] * inv;
        __syncthreads();   // u_out[i] visible to this block before next iteration
    }
}

// ---------------------------------------------------------------------------
// 2) Apply x @ Q where Q = prod_i (I - 2 u_i u_i^T), applied i = 0..RANK-1.
//    One block per row; row held in registers (8 floats/thread).
// ---------------------------------------------------------------------------
__global__ void __launch_bounds__(256) hh_kernel(const float* __restrict__ x,
                                                 const float* __restrict__ u,
                                                 float* __restrict__ xq) {
    __shared__ float sred[8];
    const int row = blockIdx.x;
    const int tid = threadIdx.x;
    const float* xr = x + (size_t)row * D_IN;

    float v[8];
    #pragma unroll
    for (int j = 0; j < 8; j++) v[j] = xr[tid + j * 256];

    for (int i = 0; i < RANK; i++) {
        const float* ui = u + (size_t)i * D_IN;
        float uu[8];
        #pragma unroll
        for (int j = 0; j < 8; j++) uu[j] = ui[tid + j * 256];
        float local = 0.f;
        #pragma unroll
        for (int j = 0; j < 8; j++) local += v[j] * uu[j];
        float dot = blockReduceSum256(local, sred);
        float s = 2.0f * dot;
        #pragma unroll
        for (int j = 0; j < 8; j++) v[j] -= s * uu[j];
    }

    float* o = xq + (size_t)row * D_IN;
    #pragma unroll
    for (int j = 0; j < 8; j++) o[tid + j * 256] = v[j];
}

// ---------------------------------------------------------------------------
// 3) SGEMM: C[M,N] = A[M,K] (row-major) * B[K,N] (row-major), fused epilogue.
//    128x128 tile, BK=8, double-buffered smem, 256 threads, 8x8 micro-tile.
//    EPI == 0 : C = gelu_exact(A*B)
//    EPI == 1 : C = A*B + bias[n]
// ---------------------------------------------------------------------------
template<int EPI>
__global__ void __launch_bounds__(256, 2) sgemm128(const float* __restrict__ A,
                                                   const float* __restrict__ B,
                                                   float* __restrict__ C,
                                                   const float* __restrict__ bias,
                                                   int M, int N, int K) {
    constexpr int BM = 128, BN = 128, BK = 8;
    __shared__ float As[2][BK][BM];
    __shared__ float Bs[2][BK][BN];

    const int tid = threadIdx.x;
    const int m0 = blockIdx.y * BM;
    const int n0 = blockIdx.x * BN;

    const int tx = tid & 15;    // n micro-tile
    const int ty = tid >> 4;    // m micro-tile

    // global->smem load mapping (one float4 from A and one from B per thread)
    const int aRow = tid >> 1;
    const int aCol = (tid & 1) << 2;
    const int bRow = tid >> 5;
    const int bCol = (tid & 31) << 2;

    const float* Ag = A + (size_t)(m0 + aRow) * K + aCol;
    const float* Bg = B + (size_t)bRow * N + n0 + bCol;

    float acc[8][8];
    #pragma unroll
    for (int i = 0; i < 8; i++)
        #pragma unroll
        for (int j = 0; j < 8; j++) acc[i][j] = 0.f;

    // preload tile 0
    float4 a4 = *(const float4*)(Ag);
    float4 b4 = *(const float4*)(Bg);
    As[0][aCol + 0][aRow] = a4.x;
    As[0][aCol + 1][aRow] = a4.y;
    As[0][aCol + 2][aRow] = a4.z;
    As[0][aCol + 3][aRow] = a4.w;
    *(float4*)&Bs[0][bRow][bCol] = b4;
    __syncthreads();

    const int nt = K / BK;
    int buf = 0;
    for (int t = 0; t < nt; t++) {
        if (t + 1 < nt) {
            a4 = *(const float4*)(Ag + (size_t)(t + 1) * BK);
            b4 = *(const float4*)(Bg + (size_t)(t + 1) * BK * N);
        }
        #pragma unroll
        for (int k = 0; k < BK; k++) {
            float af[8], bf[8];
            *(float4*)&af[0] = *(const float4*)&As[buf][k][ty * 8];
            *(float4*)&af[4] = *(const float4*)&As[buf][k][ty * 8 + 4];
            *(float4*)&bf[0] = *(const float4*)&Bs[buf][k][tx * 8];
            *(float4*)&bf[4] = *(const float4*)&Bs[buf][k][tx * 8 + 4];
            #pragma unroll
            for (int i = 0; i < 8; i++)
                #pragma unroll
                for (int j = 0; j < 8; j++)
                    acc[i][j] = fmaf(af[i], bf[j], acc[i][j]);
        }
        if (t + 1 < nt) {
            const int nb = buf ^ 1;
            As[nb][aCol + 0][aRow] = a4.x;
            As[nb][aCol + 1][aRow] = a4.y;
            As[nb][aCol + 2][aRow] = a4.z;
            As[nb][aCol + 3][aRow] = a4.w;
            *(float4*)&Bs[nb][bRow][bCol] = b4;
            __syncthreads();
            buf = nb;
        }
    }

    // epilogue
    const int cm = m0 + ty * 8;
    const int cn = n0 + tx * 8;
    float bv[8];
    if (EPI == 1) {
        #pragma unroll
        for (int j = 0; j < 8; j++) bv[j] = bias[cn + j];
    }
    #pragma unroll
    for (int i = 0; i < 8; i++) {
        float* Cp = C + (size_t)(cm + i) * N + cn;
        #pragma unroll
        for (int j = 0; j < 8; j += 4) {
            float4 v;
            v.x = acc[i][j + 0];
            v.y = acc[i][j + 1];
            v.z = acc[i][j + 2];
            v.w = acc[i][j + 3];
            if (EPI == 0) {
                v.x = 0.5f * v.x * (1.0f + erff(v.x * 0.70710678118654752f));
                v.y = 0.5f * v.y * (1.0f + erff(v.y * 0.70710678118654752f));
                v.z = 0.5f * v.z * (1.0f + erff(v.z * 0.70710678118654752f));
                v.w = 0.5f * v.w * (1.0f + erff(v.w * 0.70710678118654752f));
            } else {
                v.x += bv[j + 0];
                v.y += bv[j + 1];
                v.z += bv[j + 2];
                v.w += bv[j + 3];
            }
            *(float4*)(Cp + j) = v;
        }
    }
}

// ---------------------------------------------------------------------------
// Launcher (graph-capturable: kernel launches only)
// inputs: 0=x, 1=hra_u, 2=W_random, 3=W_out, 4=bias ; out = fp32 [4096,2048]
// ---------------------------------------------------------------------------
extern "C" void kernel_launch(void* const* d_in, const int* in_sizes, int n_in,
                              void* d_out, int out_size) {
    const float* x        = (const float*)d_in[0];
    const float* hra_u    = (const float*)d_in[1];
    const float* W_random = (const float*)d_in[2];
    const float* W_out    = (const float*)d_in[3];
    const float* bias     = (const float*)d_in[4];
    float*       out      = (float*)d_out;

    float *u_ptr = nullptr, *xq_ptr = nullptr, *h_ptr = nullptr;
    cudaGetSymbolAddress((void**)&u_ptr,  g_u);
    cudaGetSymbolAddress((void**)&xq_ptr, g_xq);
    cudaGetSymbolAddress((void**)&h_ptr,  g_h);

    gs_kernel<<<1, 256>>>(hra_u, u_ptr);
    hh_kernel<<<N_ROWS, 256>>>(x, u_ptr, xq_ptr);

    dim3 g1(D_HID / 128, N_ROWS / 128);
    sgemm128<0><<<g1, 256>>>(xq_ptr, W_random, h_ptr, nullptr, N_ROWS, D_HID, D_IN);

    dim3 g2(D_OUT / 128, N_ROWS / 128);
    sgemm128<1><<<g2, 256>>>(h_ptr, W_out, out, bias, N_ROWS, D_OUT, D_HID);
}

// round 4
// speedup vs baseline: 2.2895x; 2.2895x over previous
#include <cuda_runtime.h>
#include <cuda_bf16.h>
#include <math.h>
#include <stdint.h>

#define N_ROWS 4096
#define D_IN   2048
#define D_HID  8192
#define D_OUT  2048
#define RANK   8

// ---------------------------------------------------------------------------
// Static device scratch (no allocations allowed)
// ---------------------------------------------------------------------------
__device__ float g_u[RANK * D_IN];
__device__ __nv_bfloat16 g_xq_hi[(size_t)N_ROWS * D_IN];
__device__ __nv_bfloat16 g_xq_lo[(size_t)N_ROWS * D_IN];
__device__ __nv_bfloat16 g_wt_hi[(size_t)D_HID * D_IN];   // W_random^T [8192,2048]
__device__ __nv_bfloat16 g_wt_lo[(size_t)D_HID * D_IN];
__device__ __nv_bfloat16 g_wo_hi[(size_t)D_OUT * D_HID];  // W_out^T    [2048,8192]
__device__ __nv_bfloat16 g_wo_lo[(size_t)D_OUT * D_HID];
__device__ __nv_bfloat16 g_h_hi[(size_t)N_ROWS * D_HID];
__device__ __nv_bfloat16 g_h_lo[(size_t)N_ROWS * D_HID];

// ---------------------------------------------------------------------------
// sm_80-era PTX helpers (valid on compute_103 family target)
// ---------------------------------------------------------------------------
__device__ __forceinline__ uint32_t smem_u32(const void* p) {
    uint32_t a;
    asm("{ .reg .u64 t; cvta.to.shared.u64 t, %1; cvt.u32.u64 %0, t; }" : "=r"(a) : "l"(p));
    return a;
}
__device__ __forceinline__ void cp16(uint32_t s, const void* g) {
    asm volatile("cp.async.cg.shared.global [%0], [%1], 16;" :: "r"(s), "l"(g));
}
#define CP_COMMIT() asm volatile("cp.async.commit_group;" ::: "memory")
#define CP_WAIT(n)  asm volatile("cp.async.wait_group %0;" :: "n"(n) : "memory")

#define LDSM4(r0, r1, r2, r3, addr) \
    asm volatile("ldmatrix.sync.aligned.m8n8.x4.shared.b16 {%0,%1,%2,%3}, [%4];" \
                 : "=r"(r0), "=r"(r1), "=r"(r2), "=r"(r3) : "r"(addr))

#define MMA_BF16(c, a, b0, b1) \
    asm volatile("mma.sync.aligned.m16n8k16.row.col.f32.bf16.bf16.f32 " \
                 "{%0,%1,%2,%3},{%4,%5,%6,%7},{%8,%9},{%0,%1,%2,%3};" \
                 : "+f"((c)[0]), "+f"((c)[1]), "+f"((c)[2]), "+f"((c)[3]) \
                 : "r"((a)[0]), "r"((a)[1]), "r"((a)[2]), "r"((a)[3]), "r"(b0), "r"(b1))

// ---------------------------------------------------------------------------
// Block reduction (256 threads)
// ---------------------------------------------------------------------------
__device__ __forceinline__ float blockReduceSum256(float v, float* sred) {
    #pragma unroll
    for (int o = 16; o > 0; o >>= 1) v += __shfl_down_sync(0xffffffffu, v, o);
    const int lane = threadIdx.x & 31;
    const int warp = threadIdx.x >> 5;
    if (lane == 0) sred[warp] = v;
    __syncthreads();
    if (threadIdx.x == 0) {
        float r = sred[0];
        #pragma unroll
        for (int i = 1; i < 8; i++) r += sred[i];
        sred[0] = r;
    }
    __syncthreads();
    float r = sred[0];
    __syncthreads();
    return r;
}

// ---------------------------------------------------------------------------
// 1) Modified Gram-Schmidt (matches reference order and eps)
// ---------------------------------------------------------------------------
__global__ void gs_kernel(const float* __restrict__ hra_u, float* __restrict__ u_out) {
    __shared__ float cur[D_IN];
    __shared__ float sred[8];
    const int tid = threadIdx.x;

    for (int i = 0; i < RANK; i++) {
        for (int d = tid; d < D_IN; d += 256) cur[d] = hra_u[(size_t)d * RANK + i];
        __syncthreads();
        for (int j = 0; j < i; j++) {
            const float* uj = u_out + (size_t)j * D_IN;
            float local = 0.f;
            for (int d = tid; d < D_IN; d += 256) local += uj[d] * cur[d];
            float dot = blockReduceSum256(local, sred);
            for (int d = tid; d < D_IN; d += 256) cur[d] -= dot * uj[d];
            __syncthreads();
        }
        float local = 0.f;
        for (int d = tid; d < D_IN; d += 256) local += cur[d] * cur[d];
        float nrm2 = blockReduceSum256(local, sred);
        float inv = 1.0f / (sqrtf(nrm2) + 1e-6f);
        for (int d = tid; d < D_IN; d += 256) u_out[(size_t)i * D_IN + d] = cur[d] * inv;
        __syncthreads();
    }
}

// ---------------------------------------------------------------------------
// 2) x @ Q via 8 Householder reflections; emit bf16 hi/lo split of result
// ---------------------------------------------------------------------------
__global__ void __launch_bounds__(256) hh_kernel(const float* __restrict__ x,
                                                 const float* __restrict__ u,
                                                 __nv_bfloat16* __restrict__ xq_hi,
                                                 __nv_bfloat16* __restrict__ xq_lo) {
    __shared__ float sred[8];
    const int row = blockIdx.x;
    const int tid = threadIdx.x;
    const float* xr = x + (size_t)row * D_IN;

    float v[8];
    #pragma unroll
    for (int j = 0; j < 8; j++) v[j] = xr[tid + j * 256];

    for (int i = 0; i < RANK; i++) {
        const float* ui = u + (size_t)i * D_IN;
        float uu[8];
        #pragma unroll
        for (int j = 0; j < 8; j++) uu[j] = ui[tid + j * 256];
        float local = 0.f;
        #pragma unroll
        for (int j = 0; j < 8; j++) local += v[j] * uu[j];
        float dot = blockReduceSum256(local, sred);
        float s = 2.0f * dot;
        #pragma unroll
        for (int j = 0; j < 8; j++) v[j] -= s * uu[j];
    }

    #pragma unroll
    for (int j = 0; j < 8; j++) {
        size_t o = (size_t)row * D_IN + tid + j * 256;
        __nv_bfloat16 h = __float2bfloat16(v[j]);
        xq_hi[o] = h;
        xq_lo[o] = __float2bfloat16(v[j] - __bfloat162float(h));
    }
}

// ---------------------------------------------------------------------------
// 3) Transpose + bf16 hi/lo split: in[R,C] fp32 -> out[C,R] bf16 x2
// ---------------------------------------------------------------------------
__global__ void __launch_bounds__(256) transpose_split_kernel(
    const float* __restrict__ in, __nv_bfloat16* __restrict__ ohi,
    __nv_bfloat16* __restrict__ olo, int R, int C) {
    __shared__ float tile[32][33];
    const int c0 = blockIdx.x * 32, r0 = blockIdx.y * 32;
    const int tx = threadIdx.x, ty = threadIdx.y;
    #pragma unroll
    for (int j = 0; j < 32; j += 8)
        tile[ty + j][tx] = in[(size_t)(r0 + ty + j) * C + c0 + tx];
    __syncthreads();
    #pragma unroll
    for (int j = 0; j < 32; j += 8) {
        float v = tile[tx][ty + j];
        __nv_bfloat16 h = __float2bfloat16(v);
        size_t o = (size_t)(c0 + ty + j) * R + r0 + tx;
        ohi[o] = h;
        olo[o] = __float2bfloat16(v - __bfloat162float(h));
    }
}

// ---------------------------------------------------------------------------
// 4) HMMA GEMM: C[M,N] = A[M,K] * B[N,K]^T, bf16 3-term split, fp32 accum.
//    Block tile 128x128, BK=32, 8 warps (warp tile 32x64), 3-stage cp.async.
//    SMEM rows padded to 80 B -> conflict-free ldmatrix without swizzle.
//    EPI 0: gelu_exact -> bf16 hi/lo out (ldc = D_HID)
//    EPI 1: + bias     -> fp32 out       (ldc = D_OUT)
// ---------------------------------------------------------------------------
#define BM 128
#define BN 128
#define BK 32
#define STAGES 3
#define LDS_ROW 80                    // bytes per padded smem row (40 bf16)
#define TILE_BYTES  (128 * LDS_ROW)   // 10240
#define STAGE_BYTES (4 * TILE_BYTES)  // 40960 (Ahi, Alo, Bhi, Blo)
#define GEMM_SMEM (STAGES * STAGE_BYTES)  // 122880

__device__ __forceinline__ void load_stage(uint32_t sb,
                                           const __nv_bfloat16* __restrict__ Ahi,
                                           const __nv_bfloat16* __restrict__ Alo,
                                           const __nv_bfloat16* __restrict__ Bhi,
                                           const __nv_bfloat16* __restrict__ Blo,
                                           int m0, int n0, int kc, int K, int tid) {
    #pragma unroll
    for (int i = 0; i < 2; i++) {
        const int id = tid + i * 256;     // 512 16B-chunks per tile
        const int r = id >> 2;
        const int c = id & 3;
        const size_t ga = (size_t)(m0 + r) * K + kc + c * 8;
        const size_t gb = (size_t)(n0 + r) * K + kc + c * 8;
        const uint32_t so = (uint32_t)(r * LDS_ROW + c * 16);
        cp16(sb + so,                  Ahi + ga);
        cp16(sb + TILE_BYTES + so,     Alo + ga);
        cp16(sb + 2 * TILE_BYTES + so, Bhi + gb);
        cp16(sb + 3 * TILE_BYTES + so, Blo + gb);
    }
}

template<int EPI>
__global__ void __launch_bounds__(256, 1) gemm_hmma_x3(
    const __nv_bfloat16* __restrict__ Ahi, const __nv_bfloat16* __restrict__ Alo,
    const __nv_bfloat16* __restrict__ Bhi, const __nv_bfloat16* __restrict__ Blo,
    float* __restrict__ Cf, __nv_bfloat16* __restrict__ Chi, __nv_bfloat16* __restrict__ Clo,
    const float* __restrict__ bias, int K, int ldc) {
    extern __shared__ char smem[];
    const uint32_t sb = smem_u32(smem);
    const int tid = threadIdx.x;
    const int lane = tid & 31;
    const int wid = tid >> 5;
    const int wm = wid & 3;           // 4 warps along M (32 rows each)
    const int wn = wid >> 2;          // 2 warps along N (64 cols each)
    const int m0 = blockIdx.y * BM;
    const int n0 = blockIdx.x * BN;

    float acc[2][8][4];
    #pragma unroll
    for (int i = 0; i < 2; i++)
        #pragma unroll
        for (int j = 0; j < 8; j++)
            #pragma unroll
            for (int q = 0; q < 4; q++) acc[i][j][q] = 0.f;

    const int NT = K / BK;

    // prologue: stages 0..STAGES-2
    #pragma unroll
    for (int s = 0; s < STAGES - 1; s++) {
        load_stage(sb + s * STAGE_BYTES, Ahi, Alo, Bhi, Blo, m0, n0, s * BK, K, tid);
        CP_COMMIT();
    }

    // ldmatrix base addresses (per warp/lane, stage-relative)
    const uint32_t a_off = (uint32_t)((wm * 32 + (lane & 15)) * LDS_ROW + ((lane >> 4) << 4));
    const uint32_t b_off = (uint32_t)(2 * TILE_BYTES +
        (wn * 64 + (lane & 7) + ((lane >> 4) << 3)) * LDS_ROW + (((lane >> 3) & 1) << 4));

    for (int t = 0; t < NT; t++) {
        CP_WAIT(STAGES - 2);
        __syncthreads();

        // issue loads for stage t+STAGES-1 (overwrites stage finished at t-1)
        if (t + STAGES - 1 < NT)
            load_stage(sb + ((t + STAGES - 1) % STAGES) * STAGE_BYTES,
                       Ahi, Alo, Bhi, Blo, m0, n0, (t + STAGES - 1) * BK, K, tid);
        CP_COMMIT();

        const uint32_t st = sb + (t % STAGES) * STAGE_BYTES;
        #pragma unroll
        for (int k16 = 0; k16 < 2; k16++) {
            uint32_t ah[2][4], al[2][4], bh[4][4], bl[4][4];
            #pragma unroll
            for (int mt = 0; mt < 2; mt++) {
                const uint32_t aa = st + a_off + mt * 16 * LDS_ROW + k16 * 32;
                LDSM4(ah[mt][0], ah[mt][1], ah[mt][2], ah[mt][3], aa);
                LDSM4(al[mt][0], al[mt][1], al[mt][2], al[mt][3], aa + TILE_BYTES);
            }
            #pragma unroll
            for (int np = 0; np < 4; np++) {
                const uint32_t ba = st + b_off + np * 16 * LDS_ROW + k16 * 32;
                LDSM4(bh[np][0], bh[np][1], bh[np][2], bh[np][3], ba);
                LDSM4(bl[np][0], bl[np][1], bl[np][2], bl[np][3], ba + TILE_BYTES);
            }
            #pragma unroll
            for (int mt = 0; mt < 2; mt++) {
                #pragma unroll
                for (int np = 0; np < 4; np++) {
                    MMA_BF16(acc[mt][2 * np],     ah[mt], bh[np][0], bh[np][1]);
                    MMA_BF16(acc[mt][2 * np],     ah[mt], bl[np][0], bl[np][1]);
                    MMA_BF16(acc[mt][2 * np],     al[mt], bh[np][0], bh[np][1]);
                    MMA_BF16(acc[mt][2 * np + 1], ah[mt], bh[np][2], bh[np][3]);
                    MMA_BF16(acc[mt][2 * np + 1], ah[mt], bl[np][2], bl[np][3]);
                    MMA_BF16(acc[mt][2 * np + 1], al[mt], bh[np][2], bh[np][3]);
                }
            }
        }
    }

    // ---- epilogue (register fragments only; no smem needed)
    #pragma unroll
    for (int mt = 0; mt < 2; mt++) {
        const int r0 = m0 + wm * 32 + mt * 16 + (lane >> 2);
        #pragma unroll
        for (int nt = 0; nt < 8; nt++) {
            const int col = n0 + wn * 64 + nt * 8 + (lane & 3) * 2;
            const float* a4 = acc[mt][nt];
            if (EPI == 0) {
                #pragma unroll
                for (int h = 0; h < 2; h++) {            // h=0: row r0, h=1: row r0+8
                    const int rr = r0 + h * 8;
                    float v0 = a4[2 * h + 0], v1 = a4[2 * h + 1];
                    v0 = 0.5f * v0 * (1.0f + erff(v0 * 0.70710678118654752f));
                    v1 = 0.5f * v1 * (1.0f + erff(v1 * 0.70710678118654752f));
                    __nv_bfloat16 h0 = __float2bfloat16(v0);
                    __nv_bfloat16 h1 = __float2bfloat16(v1);
                    __nv_bfloat16 l0 = __float2bfloat16(v0 - __bfloat162float(h0));
                    __nv_bfloat16 l1 = __float2bfloat16(v1 - __bfloat162float(h1));
                    uint32_t ph = (uint32_t)__bfloat16_as_ushort(h0) |
                                  ((uint32_t)__bfloat16_as_ushort(h1) << 16);
                    uint32_t pl = (uint32_t)__bfloat16_as_ushort(l0) |
                                  ((uint32_t)__bfloat16_as_ushort(l1) << 16);
                    *(uint32_t*)(Chi + (size_t)rr * ldc + col) = ph;
                    *(uint32_t*)(Clo + (size_t)rr * ldc + col) = pl;
                }
            } else {
                const float b0 = __ldg(bias + col);
                const float b1 = __ldg(bias + col + 1);
                #pragma unroll
                for (int h = 0; h < 2; h++) {
                    const int rr = r0 + h * 8;
                    float2 v;
                    v.x = a4[2 * h + 0] + b0;
                    v.y = a4[2 * h + 1] + b1;
                    *(float2*)(Cf + (size_t)rr * ldc + col) = v;
                }
            }
        }
    }
}

// ---------------------------------------------------------------------------
// Launcher (graph-capturable)
// inputs: 0=x, 1=hra_u, 2=W_random, 3=W_out, 4=bias ; out fp32 [4096,2048]
// ---------------------------------------------------------------------------
extern "C" void kernel_launch(void* const* d_in, const int* in_sizes, int n_in,
                              void* d_out, int out_size) {
    const float* x        = (const float*)d_in[0];
    const float* hra_u    = (const float*)d_in[1];
    const float* W_random = (const float*)d_in[2];
    const float* W_out    = (const float*)d_in[3];
    const float* bias     = (const float*)d_in[4];
    float*       out      = (float*)d_out;

    float *u_p; __nv_bfloat16 *xqh, *xql, *wth, *wtl, *woh, *wol, *hh, *hl;
    cudaGetSymbolAddress((void**)&u_p,  g_u);
    cudaGetSymbolAddress((void**)&xqh,  g_xq_hi);
    cudaGetSymbolAddress((void**)&xql,  g_xq_lo);
    cudaGetSymbolAddress((void**)&wth,  g_wt_hi);
    cudaGetSymbolAddress((void**)&wtl,  g_wt_lo);
    cudaGetSymbolAddress((void**)&woh,  g_wo_hi);
    cudaGetSymbolAddress((void**)&wol,  g_wo_lo);
    cudaGetSymbolAddress((void**)&hh,   g_h_hi);
    cudaGetSymbolAddress((void**)&hl,   g_h_lo);

    cudaFuncSetAttribute(gemm_hmma_x3<0>, cudaFuncAttributeMaxDynamicSharedMemorySize, GEMM_SMEM);
    cudaFuncSetAttribute(gemm_hmma_x3<1>, cudaFuncAttributeMaxDynamicSharedMemorySize, GEMM_SMEM);

    gs_kernel<<<1, 256>>>(hra_u, u_p);
    hh_kernel<<<N_ROWS, 256>>>(x, u_p, xqh, xql);

    transpose_split_kernel<<<dim3(D_HID / 32, D_IN / 32), dim3(32, 8)>>>(W_random, wth, wtl, D_IN, D_HID);
    transpose_split_kernel<<<dim3(D_OUT / 32, D_HID / 32), dim3(32, 8)>>>(W_out, woh, wol, D_HID, D_OUT);

    // GEMM1: h = gelu(xq @ W_t)   M=4096, N=8192, K=2048
    gemm_hmma_x3<0><<<dim3(D_HID / BN, N_ROWS / BM), 256, GEMM_SMEM>>>(
        xqh, xql, wth, wtl, nullptr, hh, hl, nullptr, D_IN, D_HID);

    // GEMM2: out = h @ W_out + bias   M=4096, N=2048, K=8192
    gemm_hmma_x3<1><<<dim3(D_OUT / BN, N_ROWS / BM), 256, GEMM_SMEM>>>(
        hh, hl, woh, wol, out, nullptr, nullptr, bias, D_HID, D_OUT);
}

// round 5
// speedup vs baseline: 2.5383x; 1.1087x over previous
#include <cuda_runtime.h>
#include <cuda_bf16.h>
#include <math.h>
#include <stdint.h>

#define N_ROWS 4096
#define D_IN   2048
#define D_HID  8192
#define D_OUT  2048
#define RANK   8

// ---------------------------------------------------------------------------
// Static device scratch
// ---------------------------------------------------------------------------
__device__ float g_u[RANK * D_IN];
__device__ __nv_bfloat16 g_xq_hi[(size_t)N_ROWS * D_IN];
__device__ __nv_bfloat16 g_xq_lo[(size_t)N_ROWS * D_IN];
__device__ __nv_bfloat16 g_wt_hi[(size_t)D_HID * D_IN];   // W_random^T [8192,2048]
__device__ __nv_bfloat16 g_wt_lo[(size_t)D_HID * D_IN];
__device__ __nv_bfloat16 g_wo_hi[(size_t)D_OUT * D_HID];  // W_out^T    [2048,8192]
__device__ __nv_bfloat16 g_wo_lo[(size_t)D_OUT * D_HID];
__device__ __nv_bfloat16 g_h_hi[(size_t)N_ROWS * D_HID];
__device__ __nv_bfloat16 g_h_lo[(size_t)N_ROWS * D_HID];

// ---------------------------------------------------------------------------
// PTX helpers
// ---------------------------------------------------------------------------
__device__ __forceinline__ uint32_t smem_u32(const void* p) {
    uint32_t a;
    asm("{ .reg .u64 t; cvta.to.shared.u64 t, %1; cvt.u32.u64 %0, t; }" : "=r"(a) : "l"(p));
    return a;
}
__device__ __forceinline__ void cp16(uint32_t s, const void* g) {
    asm volatile("cp.async.cg.shared.global [%0], [%1], 16;" :: "r"(s), "l"(g));
}
#define CP_COMMIT() asm volatile("cp.async.commit_group;" ::: "memory")
#define CP_WAIT(n)  asm volatile("cp.async.wait_group %0;" :: "n"(n) : "memory")

#define LDSM4(r0, r1, r2, r3, addr) \
    asm volatile("ldmatrix.sync.aligned.m8n8.x4.shared.b16 {%0,%1,%2,%3}, [%4];" \
                 : "=r"(r0), "=r"(r1), "=r"(r2), "=r"(r3) : "r"(addr))

#define MMA_BF16(c, a, b0, b1) \
    asm volatile("mma.sync.aligned.m16n8k16.row.col.f32.bf16.bf16.f32 " \
                 "{%0,%1,%2,%3},{%4,%5,%6,%7},{%8,%9},{%0,%1,%2,%3};" \
                 : "+f"((c)[0]), "+f"((c)[1]), "+f"((c)[2]), "+f"((c)[3]) \
                 : "r"((a)[0]), "r"((a)[1]), "r"((a)[2]), "r"((a)[3]), "r"(b0), "r"(b1))

// ---------------------------------------------------------------------------
// Block reduction (256 threads)
// ---------------------------------------------------------------------------
__device__ __forceinline__ float blockReduceSum256(float v, float* sred) {
    #pragma unroll
    for (int o = 16; o > 0; o >>= 1) v += __shfl_down_sync(0xffffffffu, v, o);
    const int lane = threadIdx.x & 31;
    const int warp = threadIdx.x >> 5;
    if (lane == 0) sred[warp] = v;
    __syncthreads();
    if (threadIdx.x == 0) {
        float r = sred[0];
        #pragma unroll
        for (int i = 1; i < 8; i++) r += sred[i];
        sred[0] = r;
    }
    __syncthreads();
    float r = sred[0];
    __syncthreads();
    return r;
}

// ---------------------------------------------------------------------------
// 1) Modified Gram-Schmidt
// ---------------------------------------------------------------------------
__global__ void gs_kernel(const float* __restrict__ hra_u, float* __restrict__ u_out) {
    __shared__ float cur[D_IN];
    __shared__ float sred[8];
    const int tid = threadIdx.x;

    for (int i = 0; i < RANK; i++) {
        for (int d = tid; d < D_IN; d += 256) cur[d] = hra_u[(size_t)d * RANK + i];
        __syncthreads();
        for (int j = 0; j < i; j++) {
            const float* uj = u_out + (size_t)j * D_IN;
            float local = 0.f;
            for (int d = tid; d < D_IN; d += 256) local += uj[d] * cur[d];
            float dot = blockReduceSum256(local, sred);
            for (int d = tid; d < D_IN; d += 256) cur[d] -= dot * uj[d];
            __syncthreads();
        }
        float local = 0.f;
        for (int d = tid; d < D_IN; d += 256) local += cur[d] * cur[d];
        float nrm2 = blockReduceSum256(local, sred);
        float inv = 1.0f / (sqrtf(nrm2) + 1e-6f);
        for (int d = tid; d < D_IN; d += 256) u_out[(size_t)i * D_IN + d] = cur[d] * inv;
        __syncthreads();
    }
}

// ---------------------------------------------------------------------------
// 2) x @ Q via Householder reflections; emit bf16 hi/lo
// ---------------------------------------------------------------------------
__global__ void __launch_bounds__(256) hh_kernel(const float* __restrict__ x,
                                                 const float* __restrict__ u,
                                                 __nv_bfloat16* __restrict__ xq_hi,
                                                 __nv_bfloat16* __restrict__ xq_lo) {
    __shared__ float sred[8];
    const int row = blockIdx.x;
    const int tid = threadIdx.x;
    const float* xr = x + (size_t)row * D_IN;

    float v[8];
    #pragma unroll
    for (int j = 0; j < 8; j++) v[j] = xr[tid + j * 256];

    for (int i = 0; i < RANK; i++) {
        const float* ui = u + (size_t)i * D_IN;
        float uu[8];
        #pragma unroll
        for (int j = 0; j < 8; j++) uu[j] = ui[tid + j * 256];
        float local = 0.f;
        #pragma unroll
        for (int j = 0; j < 8; j++) local += v[j] * uu[j];
        float dot = blockReduceSum256(local, sred);
        float s = 2.0f * dot;
        #pragma unroll
        for (int j = 0; j < 8; j++) v[j] -= s * uu[j];
    }

    #pragma unroll
    for (int j = 0; j < 8; j++) {
        size_t o = (size_t)row * D_IN + tid + j * 256;
        __nv_bfloat16 h = __float2bfloat16(v[j]);
        xq_hi[o] = h;
        xq_lo[o] = __float2bfloat16(v[j] - __bfloat162float(h));
    }
}

// ---------------------------------------------------------------------------
// 3) Transpose + bf16 hi/lo split
// ---------------------------------------------------------------------------
__global__ void __launch_bounds__(256) transpose_split_kernel(
    const float* __restrict__ in, __nv_bfloat16* __restrict__ ohi,
    __nv_bfloat16* __restrict__ olo, int R, int C) {
    __shared__ float tile[32][33];
    const int c0 = blockIdx.x * 32, r0 = blockIdx.y * 32;
    const int tx = threadIdx.x, ty = threadIdx.y;
    #pragma unroll
    for (int j = 0; j < 32; j += 8)
        tile[ty + j][tx] = in[(size_t)(r0 + ty + j) * C + c0 + tx];
    __syncthreads();
    #pragma unroll
    for (int j = 0; j < 32; j += 8) {
        float v = tile[tx][ty + j];
        __nv_bfloat16 h = __float2bfloat16(v);
        size_t o = (size_t)(c0 + ty + j) * R + r0 + tx;
        ohi[o] = h;
        olo[o] = __float2bfloat16(v - __bfloat162float(h));
    }
}

// ---------------------------------------------------------------------------
// 4) HMMA GEMM: block 128x256, BK=32, 8 warps (2x4), warp tile 64x64,
//    3-stage cp.async, bf16 3-term split, fp32 accum.
//    80B-padded smem rows -> conflict-free ldmatrix.
// ---------------------------------------------------------------------------
#define BM 128
#define BN 256
#define BK 32
#define STAGES 3
#define LDS_ROW 80
#define A_TILE_B (BM * LDS_ROW)                 // 10240
#define B_TILE_B (BN * LDS_ROW)                 // 20480
#define STAGE_BYTES (2 * A_TILE_B + 2 * B_TILE_B)  // 61440: Ahi,Alo,Bhi,Blo
#define GEMM_SMEM (STAGES * STAGE_BYTES)        // 184320

__device__ __forceinline__ void load_stage(uint32_t sb,
                                           const __nv_bfloat16* __restrict__ Ahi,
                                           const __nv_bfloat16* __restrict__ Alo,
                                           const __nv_bfloat16* __restrict__ Bhi,
                                           const __nv_bfloat16* __restrict__ Blo,
                                           int m0, int n0, int kc, int K, int tid) {
    // A tiles: 128 rows x 4 x 16B ; B tiles: 256 rows x 4 x 16B
    #pragma unroll
    for (int i = 0; i < 2; i++) {                     // A hi/lo : 512 ops each
        const int id = tid + i * 256;
        const int r = id >> 2, c = id & 3;
        const size_t g = (size_t)(m0 + r) * K + kc + c * 8;
        const uint32_t so = (uint32_t)(r * LDS_ROW + c * 16);
        cp16(sb + so,            Ahi + g);
        cp16(sb + A_TILE_B + so, Alo + g);
    }
    #pragma unroll
    for (int i = 0; i < 4; i++) {                     // B hi/lo : 1024 ops each
        const int id = tid + i * 256;
        const int r = id >> 2, c = id & 3;
        const size_t g = (size_t)(n0 + r) * K + kc + c * 8;
        const uint32_t so = (uint32_t)(r * LDS_ROW + c * 16);
        cp16(sb + 2 * A_TILE_B + so,            Bhi + g);
        cp16(sb + 2 * A_TILE_B + B_TILE_B + so, Blo + g);
    }
}

template<int EPI>
__global__ void __launch_bounds__(256, 1) gemm_hmma_x3(
    const __nv_bfloat16* __restrict__ Ahi, const __nv_bfloat16* __restrict__ Alo,
    const __nv_bfloat16* __restrict__ Bhi, const __nv_bfloat16* __restrict__ Blo,
    float* __restrict__ Cf, __nv_bfloat16* __restrict__ Chi, __nv_bfloat16* __restrict__ Clo,
    const float* __restrict__ bias, int K, int ldc) {
    extern __shared__ char smem[];
    const uint32_t sb = smem_u32(smem);
    const int tid = threadIdx.x;
    const int lane = tid & 31;
    const int wid = tid >> 5;
    const int wm = wid & 1;           // 2 warps along M (64 rows each)
    const int wn = wid >> 1;          // 4 warps along N (64 cols each)
    const int m0 = blockIdx.y * BM;
    const int n0 = blockIdx.x * BN;

    float acc[4][8][4];
    #pragma unroll
    for (int i = 0; i < 4; i++)
        #pragma unroll
        for (int j = 0; j < 8; j++)
            #pragma unroll
            for (int q = 0; q < 4; q++) acc[i][j][q] = 0.f;

    const int NT = K / BK;

    #pragma unroll
    for (int s = 0; s < STAGES - 1; s++) {
        load_stage(sb + s * STAGE_BYTES, Ahi, Alo, Bhi, Blo, m0, n0, s * BK, K, tid);
        CP_COMMIT();
    }

    // ldmatrix lane-address bases (stage-relative)
    const uint32_t a_base = (uint32_t)((wm * 64 + (lane & 15)) * LDS_ROW + ((lane >> 4) << 4));
    const uint32_t b_base = (uint32_t)(2 * A_TILE_B +
        (wn * 64 + (lane & 7) + ((lane >> 4) << 3)) * LDS_ROW + (((lane >> 3) & 1) << 4));

    for (int t = 0; t < NT; t++) {
        CP_WAIT(STAGES - 2);
        __syncthreads();

        if (t + STAGES - 1 < NT)
            load_stage(sb + ((t + STAGES - 1) % STAGES) * STAGE_BYTES,
                       Ahi, Alo, Bhi, Blo, m0, n0, (t + STAGES - 1) * BK, K, tid);
        CP_COMMIT();

        const uint32_t st = sb + (t % STAGES) * STAGE_BYTES;
        #pragma unroll
        for (int k16 = 0; k16 < 2; k16++) {
            uint32_t ah[4][4], al[4][4], bh[4][4], bl[4][4];
            #pragma unroll
            for (int mt = 0; mt < 4; mt++) {
                const uint32_t aa = st + a_base + mt * 16 * LDS_ROW + k16 * 32;
                LDSM4(ah[mt][0], ah[mt][1], ah[mt][2], ah[mt][3], aa);
                LDSM4(al[mt][0], al[mt][1], al[mt][2], al[mt][3], aa + A_TILE_B);
            }
            #pragma unroll
            for (int np = 0; np < 4; np++) {
                const uint32_t ba = st + b_base + np * 16 * LDS_ROW + k16 * 32;
                LDSM4(bh[np][0], bh[np][1], bh[np][2], bh[np][3], ba);
                LDSM4(bl[np][0], bl[np][1], bl[np][2], bl[np][3], ba + B_TILE_B);
            }
            #pragma unroll
            for (int mt = 0; mt < 4; mt++) {
                #pragma unroll
                for (int np = 0; np < 4; np++) {
                    MMA_BF16(acc[mt][2 * np],     ah[mt], bh[np][0], bh[np][1]);
                    MMA_BF16(acc[mt][2 * np],     ah[mt], bl[np][0], bl[np][1]);
                    MMA_BF16(acc[mt][2 * np],     al[mt], bh[np][0], bh[np][1]);
                    MMA_BF16(acc[mt][2 * np + 1], ah[mt], bh[np][2], bh[np][3]);
                    MMA_BF16(acc[mt][2 * np + 1], ah[mt], bl[np][2], bl[np][3]);
                    MMA_BF16(acc[mt][2 * np + 1], al[mt], bh[np][2], bh[np][3]);
                }
            }
        }
    }

    // ---- epilogue (register fragments -> global)
    #pragma unroll
    for (int mt = 0; mt < 4; mt++) {
        const int r0 = m0 + wm * 64 + mt * 16 + (lane >> 2);
        #pragma unroll
        for (int nt = 0; nt < 8; nt++) {
            const int col = n0 + wn * 64 + nt * 8 + (lane & 3) * 2;
            const float* a4 = acc[mt][nt];
            if (EPI == 0) {
                #pragma unroll
                for (int h = 0; h < 2; h++) {
                    const int rr = r0 + h * 8;
                    float v0 = a4[2 * h + 0], v1 = a4[2 * h + 1];
                    v0 = 0.5f * v0 * (1.0f + erff(v0 * 0.70710678118654752f));
                    v1 = 0.5f * v1 * (1.0f + erff(v1 * 0.70710678118654752f));
                    __nv_bfloat16 h0 = __float2bfloat16(v0);
                    __nv_bfloat16 h1 = __float2bfloat16(v1);
                    __nv_bfloat16 l0 = __float2bfloat16(v0 - __bfloat162float(h0));
                    __nv_bfloat16 l1 = __float2bfloat16(v1 - __bfloat162float(h1));
                    uint32_t ph = (uint32_t)__bfloat16_as_ushort(h0) |
                                  ((uint32_t)__bfloat16_as_ushort(h1) << 16);
                    uint32_t pl = (uint32_t)__bfloat16_as_ushort(l0) |
                                  ((uint32_t)__bfloat16_as_ushort(l1) << 16);
                    *(uint32_t*)(Chi + (size_t)rr * ldc + col) = ph;
                    *(uint32_t*)(Clo + (size_t)rr * ldc + col) = pl;
                }
            } else {
                const float b0 = __ldg(bias + col);
                const float b1 = __ldg(bias + col + 1);
                #pragma unroll
                for (int h = 0; h < 2; h++) {
                    const int rr = r0 + h * 8;
                    float2 v;
                    v.x = a4[2 * h + 0] + b0;
                    v.y = a4[2 * h + 1] + b1;
                    *(float2*)(Cf + (size_t)rr * ldc + col) = v;
                }
            }
        }
    }
}

// ---------------------------------------------------------------------------
// Launcher (graph-capturable). Transposes launched first so ncu -s lands on GEMM.
// ---------------------------------------------------------------------------
extern "C" void kernel_launch(void* const* d_in, const int* in_sizes, int n_in,
                              void* d_out, int out_size) {
    const float* x        = (const float*)d_in[0];
    const float* hra_u    = (const float*)d_in[1];
    const float* W_random = (const float*)d_in[2];
    const float* W_out    = (const float*)d_in[3];
    const float* bias     = (const float*)d_in[4];
    float*       out      = (float*)d_out;

    float *u_p; __nv_bfloat16 *xqh, *xql, *wth, *wtl, *woh, *wol, *hh, *hl;
    cudaGetSymbolAddress((void**)&u_p,  g_u);
    cudaGetSymbolAddress((void**)&xqh,  g_xq_hi);
    cudaGetSymbolAddress((void**)&xql,  g_xq_lo);
    cudaGetSymbolAddress((void**)&wth,  g_wt_hi);
    cudaGetSymbolAddress((void**)&wtl,  g_wt_lo);
    cudaGetSymbolAddress((void**)&woh,  g_wo_hi);
    cudaGetSymbolAddress((void**)&wol,  g_wo_lo);
    cudaGetSymbolAddress((void**)&hh,   g_h_hi);
    cudaGetSymbolAddress((void**)&hl,   g_h_lo);

    cudaFuncSetAttribute(gemm_hmma_x3<0>, cudaFuncAttributeMaxDynamicSharedMemorySize, GEMM_SMEM);
    cudaFuncSetAttribute(gemm_hmma_x3<1>, cudaFuncAttributeMaxDynamicSharedMemorySize, GEMM_SMEM);

    transpose_split_kernel<<<dim3(D_HID / 32, D_IN / 32), dim3(32, 8)>>>(W_random, wth, wtl, D_IN, D_HID);
    transpose_split_kernel<<<dim3(D_OUT / 32, D_HID / 32), dim3(32, 8)>>>(W_out, woh, wol, D_HID, D_OUT);
    gs_kernel<<<1, 256>>>(hra_u, u_p);
    hh_kernel<<<N_ROWS, 256>>>(x, u_p, xqh, xql);

    // GEMM1: h = gelu(xq @ W_t)   M=4096, N=8192, K=2048
    gemm_hmma_x3<0><<<dim3(D_HID / BN, N_ROWS / BM), 256, GEMM_SMEM>>>(
        xqh, xql, wth, wtl, nullptr, hh, hl, nullptr, D_IN, D_HID);

    // GEMM2: out = h @ W_out + bias   M=4096, N=2048, K=8192
    gemm_hmma_x3<1><<<dim3(D_OUT / BN, N_ROWS / BM), 256, GEMM_SMEM>>>(
        hh, hl, woh, wol, out, nullptr, nullptr, bias, D_HID, D_OUT);
}

// round 6
// speedup vs baseline: 2.6428x; 1.0412x over previous
#include <cuda_runtime.h>
#include <cuda_bf16.h>
#include <math.h>
#include <stdint.h>

#define N_ROWS 4096
#define D_IN   2048
#define D_HID  8192
#define D_OUT  2048
#define RANK   8

// ---------------------------------------------------------------------------
// Static device scratch
// ---------------------------------------------------------------------------
__device__ float g_u[RANK * D_IN];
__device__ __nv_bfloat16 g_xq_hi[(size_t)N_ROWS * D_IN];
__device__ __nv_bfloat16 g_xq_lo[(size_t)N_ROWS * D_IN];
__device__ __nv_bfloat16 g_wt_hi[(size_t)D_HID * D_IN];   // W_random^T [8192,2048]
__device__ __nv_bfloat16 g_wt_lo[(size_t)D_HID * D_IN];
__device__ __nv_bfloat16 g_wo_hi[(size_t)D_OUT * D_HID];  // W_out^T    [2048,8192]
__device__ __nv_bfloat16 g_wo_lo[(size_t)D_OUT * D_HID];
__device__ __nv_bfloat16 g_h_hi[(size_t)N_ROWS * D_HID];
__device__ __nv_bfloat16 g_h_lo[(size_t)N_ROWS * D_HID];

// ---------------------------------------------------------------------------
// PTX helpers
// ---------------------------------------------------------------------------
__device__ __forceinline__ uint32_t smem_u32(const void* p) {
    uint32_t a;
    asm("{ .reg .u64 t; cvta.to.shared.u64 t, %1; cvt.u32.u64 %0, t; }" : "=r"(a) : "l"(p));
    return a;
}
__device__ __forceinline__ void cp16(uint32_t s, const void* g) {
    asm volatile("cp.async.cg.shared.global [%0], [%1], 16;" :: "r"(s), "l"(g));
}
#define CP_COMMIT() asm volatile("cp.async.commit_group;" ::: "memory")
#define CP_WAIT(n)  asm volatile("cp.async.wait_group %0;" :: "n"(n) : "memory")

#define LDSM4(r0, r1, r2, r3, addr) \
    asm volatile("ldmatrix.sync.aligned.m8n8.x4.shared.b16 {%0,%1,%2,%3}, [%4];" \
                 : "=r"(r0), "=r"(r1), "=r"(r2), "=r"(r3) : "r"(addr))

#define MMA_BF16(c, a, b0, b1) \
    asm volatile("mma.sync.aligned.m16n8k16.row.col.f32.bf16.bf16.f32 " \
                 "{%0,%1,%2,%3},{%4,%5,%6,%7},{%8,%9},{%0,%1,%2,%3};" \
                 : "+f"((c)[0]), "+f"((c)[1]), "+f"((c)[2]), "+f"((c)[3]) \
                 : "r"((a)[0]), "r"((a)[1]), "r"((a)[2]), "r"((a)[3]), "r"(b0), "r"(b1))

// ---------------------------------------------------------------------------
// Block reduction (256 threads)
// ---------------------------------------------------------------------------
__device__ __forceinline__ float blockReduceSum256(float v, float* sred) {
    #pragma unroll
    for (int o = 16; o > 0; o >>= 1) v += __shfl_down_sync(0xffffffffu, v, o);
    const int lane = threadIdx.x & 31;
    const int warp = threadIdx.x >> 5;
    if (lane == 0) sred[warp] = v;
    __syncthreads();
    if (threadIdx.x == 0) {
        float r = sred[0];
        #pragma unroll
        for (int i = 1; i < 8; i++) r += sred[i];
        sred[0] = r;
    }
    __syncthreads();
    float r = sred[0];
    __syncthreads();
    return r;
}

// ---------------------------------------------------------------------------
// 1) Modified Gram-Schmidt
// ---------------------------------------------------------------------------
__global__ void gs_kernel(const float* __restrict__ hra_u, float* __restrict__ u_out) {
    __shared__ float cur[D_IN];
    __shared__ float sred[8];
    const int tid = threadIdx.x;

    for (int i = 0; i < RANK; i++) {
        for (int d = tid; d < D_IN; d += 256) cur[d] = hra_u[(size_t)d * RANK + i];
        __syncthreads();
        for (int j = 0; j < i; j++) {
            const float* uj = u_out + (size_t)j * D_IN;
            float local = 0.f;
            for (int d = tid; d < D_IN; d += 256) local += uj[d] * cur[d];
            float dot = blockReduceSum256(local, sred);
            for (int d = tid; d < D_IN; d += 256) cur[d] -= dot * uj[d];
            __syncthreads();
        }
        float local = 0.f;
        for (int d = tid; d < D_IN; d += 256) local += cur[d] * cur[d];
        float nrm2 = blockReduceSum256(local, sred);
        float inv = 1.0f / (sqrtf(nrm2) + 1e-6f);
        for (int d = tid; d < D_IN; d += 256) u_out[(size_t)i * D_IN + d] = cur[d] * inv;
        __syncthreads();
    }
}

// ---------------------------------------------------------------------------
// 2) x @ Q via Householder reflections; emit bf16 hi/lo
// ---------------------------------------------------------------------------
__global__ void __launch_bounds__(256) hh_kernel(const float* __restrict__ x,
                                                 const float* __restrict__ u,
                                                 __nv_bfloat16* __restrict__ xq_hi,
                                                 __nv_bfloat16* __restrict__ xq_lo) {
    __shared__ float sred[8];
    const int row = blockIdx.x;
    const int tid = threadIdx.x;
    const float* xr = x + (size_t)row * D_IN;

    float v[8];
    #pragma unroll
    for (int j = 0; j < 8; j++) v[j] = xr[tid + j * 256];

    for (int i = 0; i < RANK; i++) {
        const float* ui = u + (size_t)i * D_IN;
        float uu[8];
        #pragma unroll
        for (int j = 0; j < 8; j++) uu[j] = ui[tid + j * 256];
        float local = 0.f;
        #pragma unroll
        for (int j = 0; j < 8; j++) local += v[j] * uu[j];
        float dot = blockReduceSum256(local, sred);
        float s = 2.0f * dot;
        #pragma unroll
        for (int j = 0; j < 8; j++) v[j] -= s * uu[j];
    }

    #pragma unroll
    for (int j = 0; j < 8; j++) {
        size_t o = (size_t)row * D_IN + tid + j * 256;
        __nv_bfloat16 h = __float2bfloat16(v[j]);
        xq_hi[o] = h;
        xq_lo[o] = __float2bfloat16(v[j] - __bfloat162float(h));
    }
}

// ---------------------------------------------------------------------------
// 3) Transpose + bf16 hi/lo split
// ---------------------------------------------------------------------------
__global__ void __launch_bounds__(256) transpose_split_kernel(
    const float* __restrict__ in, __nv_bfloat16* __restrict__ ohi,
    __nv_bfloat16* __restrict__ olo, int R, int C) {
    __shared__ float tile[32][33];
    const int c0 = blockIdx.x * 32, r0 = blockIdx.y * 32;
    const int tx = threadIdx.x, ty = threadIdx.y;
    #pragma unroll
    for (int j = 0; j < 32; j += 8)
        tile[ty + j][tx] = in[(size_t)(r0 + ty + j) * C + c0 + tx];
    __syncthreads();
    #pragma unroll
    for (int j = 0; j < 32; j += 8) {
        float v = tile[tx][ty + j];
        __nv_bfloat16 h = __float2bfloat16(v);
        size_t o = (size_t)(c0 + ty + j) * R + r0 + tx;
        ohi[o] = h;
        olo[o] = __float2bfloat16(v - __bfloat162float(h));
    }
}

// ---------------------------------------------------------------------------
// 4) HMMA GEMM: block 128x128, BK=32, 8 warps (2 M x 4 N), warp tile 64x32,
//    2-stage cp.async, 2 CTAs/SM (4 warps/SMSP), bf16 3-term split.
//    80B-padded smem rows -> conflict-free ldmatrix.
// ---------------------------------------------------------------------------
#define BM 128
#define BN 128
#define BK 32
#define STAGES 2
#define LDS_ROW 80
#define TILE_BYTES  (128 * LDS_ROW)             // 10240
#define STAGE_BYTES (4 * TILE_BYTES)            // 40960: Ahi,Alo,Bhi,Blo
#define GEMM_SMEM (STAGES * STAGE_BYTES)        // 81920 -> 2 CTAs/SM

__device__ __forceinline__ void load_stage(uint32_t sb,
                                           const __nv_bfloat16* __restrict__ Ahi,
                                           const __nv_bfloat16* __restrict__ Alo,
                                           const __nv_bfloat16* __restrict__ Bhi,
                                           const __nv_bfloat16* __restrict__ Blo,
                                           int m0, int n0, int kc, int K, int tid) {
    #pragma unroll
    for (int i = 0; i < 2; i++) {
        const int id = tid + i * 256;     // 512 16B-chunks per tile
        const int r = id >> 2;
        const int c = id & 3;
        const size_t ga = (size_t)(m0 + r) * K + kc + c * 8;
        const size_t gb = (size_t)(n0 + r) * K + kc + c * 8;
        const uint32_t so = (uint32_t)(r * LDS_ROW + c * 16);
        cp16(sb + so,                  Ahi + ga);
        cp16(sb + TILE_BYTES + so,     Alo + ga);
        cp16(sb + 2 * TILE_BYTES + so, Bhi + gb);
        cp16(sb + 3 * TILE_BYTES + so, Blo + gb);
    }
}

template<int EPI>
__global__ void __launch_bounds__(256, 2) gemm_hmma_x3(
    const __nv_bfloat16* __restrict__ Ahi, const __nv_bfloat16* __restrict__ Alo,
    const __nv_bfloat16* __restrict__ Bhi, const __nv_bfloat16* __restrict__ Blo,
    float* __restrict__ Cf, __nv_bfloat16* __restrict__ Chi, __nv_bfloat16* __restrict__ Clo,
    const float* __restrict__ bias, int K, int ldc) {
    extern __shared__ char smem[];
    const uint32_t sb = smem_u32(smem);
    const int tid = threadIdx.x;
    const int lane = tid & 31;
    const int wid = tid >> 5;
    const int wm = wid & 1;           // 2 warps along M (64 rows each)
    const int wn = wid >> 1;          // 4 warps along N (32 cols each)
    const int m0 = blockIdx.y * BM;
    const int n0 = blockIdx.x * BN;

    float acc[4][4][4];               // [mt][nt][frag]
    #pragma unroll
    for (int i = 0; i < 4; i++)
        #pragma unroll
        for (int j = 0; j < 4; j++)
            #pragma unroll
            for (int q = 0; q < 4; q++) acc[i][j][q] = 0.f;

    const int NT = K / BK;

    // prologue: stage 0
    load_stage(sb, Ahi, Alo, Bhi, Blo, m0, n0, 0, K, tid);
    CP_COMMIT();

    // ldmatrix lane-address bases (stage-relative)
    const uint32_t a_base = (uint32_t)((wm * 64 + (lane & 15)) * LDS_ROW + ((lane >> 4) << 4));
    const uint32_t b_base = (uint32_t)(2 * TILE_BYTES +
        (wn * 32 + (lane & 7) + ((lane >> 4) << 3)) * LDS_ROW + (((lane >> 3) & 1) << 4));

    for (int t = 0; t < NT; t++) {
        CP_WAIT(0);                    // stage t resident
        __syncthreads();

        if (t + 1 < NT)                // prefetch stage t+1 into other buffer
            load_stage(sb + ((t + 1) & 1) * STAGE_BYTES,
                       Ahi, Alo, Bhi, Blo, m0, n0, (t + 1) * BK, K, tid);
        CP_COMMIT();

        const uint32_t st = sb + (t & 1) * STAGE_BYTES;
        #pragma unroll
        for (int k16 = 0; k16 < 2; k16++) {
            uint32_t ah[4][4], al[4][4], bh[2][4], bl[2][4];
            #pragma unroll
            for (int mt = 0; mt < 4; mt++) {
                const uint32_t aa = st + a_base + mt * 16 * LDS_ROW + k16 * 32;
                LDSM4(ah[mt][0], ah[mt][1], ah[mt][2], ah[mt][3], aa);
                LDSM4(al[mt][0], al[mt][1], al[mt][2], al[mt][3], aa + TILE_BYTES);
            }
            #pragma unroll
            for (int np = 0; np < 2; np++) {
                const uint32_t ba = st + b_base + np * 16 * LDS_ROW + k16 * 32;
                LDSM4(bh[np][0], bh[np][1], bh[np][2], bh[np][3], ba);
                LDSM4(bl[np][0], bl[np][1], bl[np][2], bl[np][3], ba + TILE_BYTES);
            }
            #pragma unroll
            for (int mt = 0; mt < 4; mt++) {
                #pragma unroll
                for (int np = 0; np < 2; np++) {
                    MMA_BF16(acc[mt][2 * np],     ah[mt], bh[np][0], bh[np][1]);
                    MMA_BF16(acc[mt][2 * np],     ah[mt], bl[np][0], bl[np][1]);
                    MMA_BF16(acc[mt][2 * np],     al[mt], bh[np][0], bh[np][1]);
                    MMA_BF16(acc[mt][2 * np + 1], ah[mt], bh[np][2], bh[np][3]);
                    MMA_BF16(acc[mt][2 * np + 1], ah[mt], bl[np][2], bl[np][3]);
                    MMA_BF16(acc[mt][2 * np + 1], al[mt], bh[np][2], bh[np][3]);
                }
            }
        }
        __syncthreads();               // all reads of stage t done before overwrite
    }

    // ---- epilogue (register fragments -> global)
    #pragma unroll
    for (int mt = 0; mt < 4; mt++) {
        const int r0 = m0 + wm * 64 + mt * 16 + (lane >> 2);
        #pragma unroll
        for (int nt = 0; nt < 4; nt++) {
            const int col = n0 + wn * 32 + nt * 8 + (lane & 3) * 2;
            const float* a4 = acc[mt][nt];
            if (EPI == 0) {
                #pragma unroll
                for (int h = 0; h < 2; h++) {
                    const int rr = r0 + h * 8;
                    float v0 = a4[2 * h + 0], v1 = a4[2 * h + 1];
                    v0 = 0.5f * v0 * (1.0f + erff(v0 * 0.70710678118654752f));
                    v1 = 0.5f * v1 * (1.0f + erff(v1 * 0.70710678118654752f));
                    __nv_bfloat16 h0 = __float2bfloat16(v0);
                    __nv_bfloat16 h1 = __float2bfloat16(v1);
                    __nv_bfloat16 l0 = __float2bfloat16(v0 - __bfloat162float(h0));
                    __nv_bfloat16 l1 = __float2bfloat16(v1 - __bfloat162float(h1));
                    uint32_t ph = (uint32_t)__bfloat16_as_ushort(h0) |
                                  ((uint32_t)__bfloat16_as_ushort(h1) << 16);
                    uint32_t pl = (uint32_t)__bfloat16_as_ushort(l0) |
                                  ((uint32_t)__bfloat16_as_ushort(l1) << 16);
                    *(uint32_t*)(Chi + (size_t)rr * ldc + col) = ph;
                    *(uint32_t*)(Clo + (size_t)rr * ldc + col) = pl;
                }
            } else {
                const float b0 = __ldg(bias + col);
                const float b1 = __ldg(bias + col + 1);
                #pragma unroll
                for (int h = 0; h < 2; h++) {
                    const int rr = r0 + h * 8;
                    float2 v;
                    v.x = a4[2 * h + 0] + b0;
                    v.y = a4[2 * h + 1] + b1;
                    *(float2*)(Cf + (size_t)rr * ldc + col) = v;
                }
            }
        }
    }
}

// ---------------------------------------------------------------------------
// Launcher. Order chosen so the profiled launch (index 3) is GEMM1:
//   0: transpose(W_random)  1: gs  2: hh  3: GEMM1  4: transpose(W_out)  5: GEMM2
// ---------------------------------------------------------------------------
extern "C" void kernel_launch(void* const* d_in, const int* in_sizes, int n_in,
                              void* d_out, int out_size) {
    const float* x        = (const float*)d_in[0];
    const float* hra_u    = (const float*)d_in[1];
    const float* W_random = (const float*)d_in[2];
    const float* W_out    = (const float*)d_in[3];
    const float* bias     = (const float*)d_in[4];
    float*       out      = (float*)d_out;

    float *u_p; __nv_bfloat16 *xqh, *xql, *wth, *wtl, *woh, *wol, *hh, *hl;
    cudaGetSymbolAddress((void**)&u_p,  g_u);
    cudaGetSymbolAddress((void**)&xqh,  g_xq_hi);
    cudaGetSymbolAddress((void**)&xql,  g_xq_lo);
    cudaGetSymbolAddress((void**)&wth,  g_wt_hi);
    cudaGetSymbolAddress((void**)&wtl,  g_wt_lo);
    cudaGetSymbolAddress((void**)&woh,  g_wo_hi);
    cudaGetSymbolAddress((void**)&wol,  g_wo_lo);
    cudaGetSymbolAddress((void**)&hh,   g_h_hi);
    cudaGetSymbolAddress((void**)&hl,   g_h_lo);

    cudaFuncSetAttribute(gemm_hmma_x3<0>, cudaFuncAttributeMaxDynamicSharedMemorySize, GEMM_SMEM);
    cudaFuncSetAttribute(gemm_hmma_x3<1>, cudaFuncAttributeMaxDynamicSharedMemorySize, GEMM_SMEM);

    transpose_split_kernel<<<dim3(D_HID / 32, D_IN / 32), dim3(32, 8)>>>(W_random, wth, wtl, D_IN, D_HID);
    gs_kernel<<<1, 256>>>(hra_u, u_p);
    hh_kernel<<<N_ROWS, 256>>>(x, u_p, xqh, xql);

    // GEMM1: h = gelu(xq @ W_t)   M=4096, N=8192, K=2048
    gemm_hmma_x3<0><<<dim3(D_HID / BN, N_ROWS / BM), 256, GEMM_SMEM>>>(
        xqh, xql, wth, wtl, nullptr, hh, hl, nullptr, D_IN, D_HID);

    transpose_split_kernel<<<dim3(D_OUT / 32, D_HID / 32), dim3(32, 8)>>>(W_out, woh, wol, D_HID, D_OUT);

    // GEMM2: out = h @ W_out + bias   M=4096, N=2048, K=8192
    gemm_hmma_x3<1><<<dim3(D_OUT / BN, N_ROWS / BM), 256, GEMM_SMEM>>>(
        hh, hl, woh, wol, out, nullptr, nullptr, bias, D_HID, D_OUT);
}